// round 6
// baseline (speedup 1.0000x reference)
#include <cuda_runtime.h>
#include <cuda_bf16.h>

// Depthwise 3x3 conv, pad=1: x (2,16,256,64,64) fp32, W (256,256,3,3) -> diag only.
#define C_CH   256
#define H_SP   64
#define W_SP   64
#define N_IMG  (2 * 16 * C_CH)   // 8192 images of 64x64
#define HALF_H 32

__device__ __forceinline__ float4 f4zero() { return make_float4(0.f, 0.f, 0.f, 0.f); }

// Horizontal halo: l = previous lane's .w, r = next lane's .x, zeroed at
// the 16-lane group boundaries (each 16-lane group covers one 64-wide row).
__device__ __forceinline__ void halo(const float4& v, int lane16, float& l, float& r)
{
    l = __shfl_up_sync(0xffffffffu, v.w, 1);
    r = __shfl_down_sync(0xffffffffu, v.x, 1);
    if (lane16 == 0)  l = 0.f;
    if (lane16 == 15) r = 0.f;
}

__device__ __forceinline__ float4 conv_row(const float4& vm, float lm, float rm,
                                           const float4& vc, float lc, float rc_,
                                           const float4& vn, float ln, float rn,
                                           float w00, float w01, float w02,
                                           float w10, float w11, float w12,
                                           float w20, float w21, float w22)
{
    float4 o;
    o.x = w00*lm   + w01*vm.x + w02*vm.y
        + w10*lc   + w11*vc.x + w12*vc.y
        + w20*ln   + w21*vn.x + w22*vn.y;
    o.y = w00*vm.x + w01*vm.y + w02*vm.z
        + w10*vc.x + w11*vc.y + w12*vc.z
        + w20*vn.x + w21*vn.y + w22*vn.z;
    o.z = w00*vm.y + w01*vm.z + w02*vm.w
        + w10*vc.y + w11*vc.z + w12*vc.w
        + w20*vn.y + w21*vn.z + w22*vn.w;
    o.w = w00*vm.z + w01*vm.w + w02*rm
        + w10*vc.z + w11*vc.w + w12*rc_
        + w20*vn.z + w21*vn.w + w22*rn;
    return o;
}

__global__ __launch_bounds__(256)
void dwconv3x3_pipe_kernel(const float* __restrict__ x,
                           const float* __restrict__ Wf,
                           float* __restrict__ y)
{
    const int tid    = threadIdx.x;
    const int warp   = tid >> 5;
    const int lane   = tid & 31;
    const int lane16 = lane & 15;

    // One warp = one image. Lanes 0-15: rows [0,32). Lanes 16-31: rows [32,64).
    const int image = blockIdx.x * 8 + warp;            // 0..8191
    const int c     = image & (C_CH - 1);
    const int top   = (lane >> 4) * HALF_H;             // 0 or 32
    const int col   = lane16 << 2;                      // 0,4,...,60

    // Diagonal filter W[c][c][ky][kx] — warp-uniform.
    const float* wp = Wf + (size_t)c * (C_CH + 1) * 9;
    const float w00 = __ldg(wp + 0), w01 = __ldg(wp + 1), w02 = __ldg(wp + 2);
    const float w10 = __ldg(wp + 3), w11 = __ldg(wp + 4), w12 = __ldg(wp + 5);
    const float w20 = __ldg(wp + 6), w21 = __ldg(wp + 7), w22 = __ldg(wp + 8);

    const float* xin  = x + (size_t)image * (H_SP * W_SP) + col;
    float*       yout = y + (size_t)image * (H_SP * W_SP) + col;

    // 4-row resident window: rows r-1 (a), r (b), r+1 (c), r+2 (d).
    float4 va, vb, vc4, vd;
    float  la, ra, lb, rb, lc, rc_, ld, rd;

    va  = (top >= 1) ? __ldg((const float4*)(xin + (top - 1) * W_SP)) : f4zero();
    vb  = __ldg((const float4*)(xin +  top      * W_SP));
    vc4 = __ldg((const float4*)(xin + (top + 1) * W_SP));
    vd  = __ldg((const float4*)(xin + (top + 2) * W_SP));   // top+2 <= 34, always valid
    halo(va,  lane16, la, ra);
    halo(vb,  lane16, lb, rb);
    halo(vc4, lane16, lc, rc_);
    halo(vd,  lane16, ld, rd);

    // 2 output rows per iteration; prefetch rows r0+3, r0+4 for the NEXT iteration.
    #pragma unroll
    for (int i = 0; i < HALF_H / 2; i++) {
        const int r0 = top + 2 * i;
        const int ge = r0 + 3;
        const int gf = r0 + 4;

        // Issue both prefetch loads back-to-back; consumed only next iteration.
        float4 ve = (ge < H_SP) ? __ldg((const float4*)(xin + ge * W_SP)) : f4zero();
        float4 vf = (gf < H_SP) ? __ldg((const float4*)(xin + gf * W_SP)) : f4zero();

        // Row r0: window (a, b, c). Row r0+1: window (b, c, d). All resident.
        float4 o0 = conv_row(va, la, ra, vb, lb, rb, vc4, lc, rc_,
                             w00, w01, w02, w10, w11, w12, w20, w21, w22);
        *(float4*)(yout + r0 * W_SP) = o0;

        float4 o1 = conv_row(vb, lb, rb, vc4, lc, rc_, vd, ld, rd,
                             w00, w01, w02, w10, w11, w12, w20, w21, w22);
        *(float4*)(yout + (r0 + 1) * W_SP) = o1;

        // Halo the prefetched rows (after compute, right before they're needed).
        float le, re, lf, rf;
        halo(ve, lane16, le, re);
        halo(vf, lane16, lf, rf);

        // Slide window by 2.
        va  = vc4; la = lc;  ra = rc_;
        vb  = vd;  lb = ld;  rb = rd;
        vc4 = ve;  lc = le;  rc_ = re;
        vd  = vf;  ld = lf;  rd = rf;
    }
}

extern "C" void kernel_launch(void* const* d_in, const int* in_sizes, int n_in,
                              void* d_out, int out_size)
{
    const float* x  = (const float*)d_in[0];   // (S,B,C,H,W) fp32
    const float* Wf = (const float*)d_in[1];   // (C,C,3,3)  fp32
    float* y = (float*)d_out;

    dwconv3x3_pipe_kernel<<<N_IMG / 8, 256>>>(x, Wf, y);
}